// round 5
// baseline (speedup 1.0000x reference)
#include <cuda_runtime.h>

#define NB 128
#define NN 128
#define INNER 40
#define OUTD 512
#define FCH 41
#define ROWF (NN * FCH)          // 5248 floats per (b,i) row
#define ROWQ (ROWF / 4)          // 1312 float4

typedef unsigned long long ull;

// Scratch (allocation-free: device globals)
__device__ float g_S0[NB * NN * INNER];     // row sums over j of g[b,i,j,f], f<40
__device__ float g_core0[NB * NN * INNER];  // diagonal attrs g[b,i,i,f], f<40
__device__ float g_bonds[NB * NN * NN];     // g[b,i,j,40] laid out [b][i][j]
__device__ float g_cores[3 * NB * NN * INNER]; // cores per depth, [d][b][i][f]

// ---------------- helpers ----------------
__device__ __forceinline__ ull pk(float a, float b) {
    ull r;
    asm("mov.b64 %0, {%1,%2};" : "=l"(r) : "f"(a), "f"(b));
    return r;
}
__device__ __forceinline__ ull fma2(ull a, ull b, ull c) {
    ull d;
    asm("fma.rn.f32x2 %0, %1, %2, %3;" : "=l"(d) : "l"(a), "l"(b), "l"(c));
    return d;
}
__device__ __forceinline__ float lo64(ull v) { return __uint_as_float((unsigned)v); }
__device__ __forceinline__ float hi64(ull v) { return __uint_as_float((unsigned)(v >> 32)); }

__device__ __forceinline__ float wred_max(float v) {
#pragma unroll
    for (int o = 16; o; o >>= 1) v = fmaxf(v, __shfl_xor_sync(0xffffffffu, v, o));
    return v;
}
__device__ __forceinline__ float wred_sum(float v) {
#pragma unroll
    for (int o = 16; o; o >>= 1) v += __shfl_xor_sync(0xffffffffu, v, o);
    return v;
}

// ---------------- kernel 1: streaming row reduction, 2 rows per block ----------------
// 4*328 = 1312 = 32*41: thread t, float4 slot t+328s -> element k has channel
// f_k = (4t+k) % 41 constant in s, j = (4t+k)/41 + 32s. All 8 loads issued first (MLP=8).
__global__ void __launch_bounds__(FCH * 8) k_rowsum(const float* __restrict__ g,
                                                    float* __restrict__ out) {
    const int pr   = blockIdx.x;         // row pair 0..8191
    const int row0 = pr * 2;
    const int t    = threadIdx.x;        // 0..327
    const float4* base = reinterpret_cast<const float4*>(g + (long long)row0 * ROWF);

    __shared__ float s_flat[2][FCH * 32];   // per-row channel partials

    if (t < 2) reinterpret_cast<float4*>(out)[row0 + t] = make_float4(0.f, 0.f, 0.f, 0.f);

    // front-batched loads: 8 independent LDG.128
    float4 v[8];
#pragma unroll
    for (int s = 0; s < 4; s++) {
        v[s]     = base[t + 328 * s];
        v[4 + s] = base[ROWQ + t + 328 * s];
    }

    int f4[4], jb[4];
#pragma unroll
    for (int k = 0; k < 4; k++) {
        int e = 4 * t + k;
        f4[k] = e % FCH;
        jb[k] = e / FCH;
    }

#pragma unroll
    for (int r = 0; r < 2; r++) {
        const int row = row0 + r;
        const int i   = row & (NN - 1);
        float* brow = g_bonds + row * NN;
        float acc0 = 0.f, acc1 = 0.f, acc2 = 0.f, acc3 = 0.f;
#pragma unroll
        for (int s = 0; s < 4; s++) {
            float4 x = v[4 * r + s];
            const int j0 = 32 * s;
            if (f4[0] == FCH - 1) brow[jb[0] + j0] = x.x;
            else { acc0 += x.x; if (jb[0] + j0 == i) g_core0[row * INNER + f4[0]] = x.x; }
            if (f4[1] == FCH - 1) brow[jb[1] + j0] = x.y;
            else { acc1 += x.y; if (jb[1] + j0 == i) g_core0[row * INNER + f4[1]] = x.y; }
            if (f4[2] == FCH - 1) brow[jb[2] + j0] = x.z;
            else { acc2 += x.z; if (jb[2] + j0 == i) g_core0[row * INNER + f4[2]] = x.z; }
            if (f4[3] == FCH - 1) brow[jb[3] + j0] = x.w;
            else { acc3 += x.w; if (jb[3] + j0 == i) g_core0[row * INNER + f4[3]] = x.w; }
        }
        *reinterpret_cast<float4*>(&s_flat[r][4 * t]) = make_float4(acc0, acc1, acc2, acc3);
    }
    __syncthreads();

    if (t < INNER) {
        float t0 = 0.f, t1 = 0.f;
#pragma unroll
        for (int m = 0; m < 32; m++) {     // stride 41 mod 32 = 9, gcd(9,32)=1 -> conflict-free
            t0 += s_flat[0][t + FCH * m];
            t1 += s_flat[1][t + FCH * m];
        }
        g_S0[row0 * INNER + t]          = t0;
        g_S0[(row0 + 1) * INNER + t]    = t1;
    }
}

// ---------------- kernel 2: compute the three cores, write to global ----------------
// grid (128, 4), block 128. Same math as before; output g_cores[d][row][f].
__global__ void __launch_bounds__(128) k_cores(
    const float* __restrict__ Wi,   // (3,40,40)
    const float* __restrict__ bi)   // (3,1,40)
{
    const int b   = blockIdx.x;
    const int i0  = blockIdx.y * 32;
    const int tid = threadIdx.x;
    const int warp = tid >> 5, lane = tid & 31;

    __shared__ float shA[32][INNER + 1];   // S0, later pre2
    __shared__ float shC0[32][INNER + 1];  // core0
    __shared__ float shc[32];
    __shared__ float shcp[4][32];
    __shared__ float cores[3][INNER][32];

    for (int idx = tid; idx < 32 * INNER; idx += 128) {
        int n = idx / INNER, f2 = idx % INNER;
        int row = b * NN + i0 + n;
        shA[n][f2] = g_S0[row * INNER + f2];
        float cv = g_core0[row * INNER + f2];
        shC0[n][f2] = cv;
        cores[0][f2][n] = cv;
    }
    {
        const float* bb = g_bonds + (b * NN) * NN + i0 + lane;
        float cp = 0.f;
#pragma unroll 8
        for (int m = 0; m < 32; m++)
            cp += bb[(warp + 4 * m) * NN];
        shcp[warp][lane] = cp;
    }
    __syncthreads();
    if (tid < 32)
        shc[tid] = 1.0f + shcp[0][tid] + shcp[1][tid] + shcp[2][tid] + shcp[3][tid];
    __syncthreads();

    for (int idx = tid; idx < INNER * 32; idx += 128) {
        int fp = idx >> 5, n = idx & 31;
        float s = bi[INNER + fp];
#pragma unroll
        for (int f2 = 0; f2 < INNER; f2++)
            s = fmaf(shA[n][f2], Wi[INNER * INNER + f2 * INNER + fp], s);
        cores[1][fp][n] = s;
    }
    __syncthreads();

    for (int idx = tid; idx < INNER * 32; idx += 128) {
        int f2 = idx >> 5, n = idx & 31;
        float d1 = cores[1][f2][n] - shC0[n][f2];
        shA[n][f2] = fmaf(shc[n], d1, shA[n][f2]);
    }
    __syncthreads();

    for (int idx = tid; idx < INNER * 32; idx += 128) {
        int fp = idx >> 5, n = idx & 31;
        float s = bi[2 * INNER + fp];
#pragma unroll
        for (int f2 = 0; f2 < INNER; f2++)
            s = fmaf(shA[n][f2], Wi[2 * INNER * INNER + f2 * INNER + fp], s);
        cores[2][fp][n] = s;
    }
    __syncthreads();

    // write out: [d][b][i0+n][f], coalesced over idx
    for (int idx = tid; idx < 3 * 32 * INNER; idx += 128) {
        int f2 = idx % INNER;
        int n  = (idx / INNER) % 32;
        int d  = idx / (32 * INNER);
        g_cores[((d * NB + b) * NN + i0 + n) * INNER + f2] = cores[d][f2][n];
    }
}

// ---------------- kernel 3: logits GEMM + softmax + fp, one depth per block ----------------
// grid (128, 4, 3): batch b, node group of 32, depth d. block 128 threads (4 cols each).
__global__ void __launch_bounds__(128) k_gemm(
    const float* __restrict__ Wo,   // (3,40,512)
    const float* __restrict__ bo,   // (3,1,512)
    float* __restrict__ out)        // (128,512)
{
    const int b   = blockIdx.x;
    const int i0  = blockIdx.y * 32;
    const int d   = blockIdx.z;
    const int tid = threadIdx.x;
    const int warp = tid >> 5, lane = tid & 31;

    __shared__ __align__(16) float cores[INNER][32];
    __shared__ float redmax[4][8];
    __shared__ float redsum[4][8];

    // stage cores (coalesced global read, transpose into [f][node])
    for (int idx = tid; idx < 32 * INNER; idx += 128) {
        int f2 = idx % INNER, n = idx / INNER;
        cores[f2][n] = g_cores[((d * NB + b) * NN + i0 + n) * INNER + f2];
    }
    __syncthreads();

    float fp0 = 0.f, fp1 = 0.f, fp2 = 0.f, fp3 = 0.f;

    const float* Wd = Wo + d * (INNER * OUTD) + (tid << 2);
    float4 bv = *reinterpret_cast<const float4*>(bo + d * OUTD + (tid << 2));
    const ull bb0 = pk(bv.x, bv.x), bb1 = pk(bv.y, bv.y),
              bb2 = pk(bv.z, bv.z), bb3 = pk(bv.w, bv.w);

    for (int ch = 0; ch < 4; ch++) {   // 8 nodes per chunk (4 f32x2 pairs)
        ull acc[4][4];
#pragma unroll
        for (int p = 0; p < 4; p++) {
            acc[0][p] = bb0; acc[1][p] = bb1; acc[2][p] = bb2; acc[3][p] = bb3;
        }
        const ull* cr = reinterpret_cast<const ull*>(&cores[0][ch * 8]);
#pragma unroll 8
        for (int f2 = 0; f2 < INNER; f2++) {
            float4 w4 = *reinterpret_cast<const float4*>(Wd + f2 * OUTD);
            ull w0 = pk(w4.x, w4.x), w1 = pk(w4.y, w4.y),
                w2 = pk(w4.z, w4.z), w3 = pk(w4.w, w4.w);
            ull c0 = cr[f2 * 16 + 0], c1 = cr[f2 * 16 + 1],
                c2 = cr[f2 * 16 + 2], c3 = cr[f2 * 16 + 3];
            acc[0][0] = fma2(c0, w0, acc[0][0]);
            acc[1][0] = fma2(c0, w1, acc[1][0]);
            acc[2][0] = fma2(c0, w2, acc[2][0]);
            acc[3][0] = fma2(c0, w3, acc[3][0]);
            acc[0][1] = fma2(c1, w0, acc[0][1]);
            acc[1][1] = fma2(c1, w1, acc[1][1]);
            acc[2][1] = fma2(c1, w2, acc[2][1]);
            acc[3][1] = fma2(c1, w3, acc[3][1]);
            acc[0][2] = fma2(c2, w0, acc[0][2]);
            acc[1][2] = fma2(c2, w1, acc[1][2]);
            acc[2][2] = fma2(c2, w2, acc[2][2]);
            acc[3][2] = fma2(c2, w3, acc[3][2]);
            acc[0][3] = fma2(c3, w0, acc[0][3]);
            acc[1][3] = fma2(c3, w1, acc[1][3]);
            acc[2][3] = fma2(c3, w2, acc[2][3]);
            acc[3][3] = fma2(c3, w3, acc[3][3]);
        }

        float vl[4][4], vh[4][4];
#pragma unroll
        for (int k = 0; k < 4; k++)
#pragma unroll
            for (int p = 0; p < 4; p++) {
                vl[k][p] = lo64(acc[k][p]);
                vh[k][p] = hi64(acc[k][p]);
            }

        float ml[4], mh[4];
#pragma unroll
        for (int p = 0; p < 4; p++) {
            ml[p] = fmaxf(fmaxf(vl[0][p], vl[1][p]), fmaxf(vl[2][p], vl[3][p]));
            mh[p] = fmaxf(fmaxf(vh[0][p], vh[1][p]), fmaxf(vh[2][p], vh[3][p]));
            ml[p] = wred_max(ml[p]);
            mh[p] = wred_max(mh[p]);
        }
        if (lane == 0) {
#pragma unroll
            for (int p = 0; p < 4; p++) {
                redmax[warp][2 * p]     = ml[p];
                redmax[warp][2 * p + 1] = mh[p];
            }
        }
        __syncthreads();
        float M[8];
#pragma unroll
        for (int nn = 0; nn < 8; nn++)
            M[nn] = fmaxf(fmaxf(redmax[0][nn], redmax[1][nn]),
                          fmaxf(redmax[2][nn], redmax[3][nn]));

        float sl[4], sh2[4];
#pragma unroll
        for (int p = 0; p < 4; p++) {
            float s1 = 0.f, s2 = 0.f;
#pragma unroll
            for (int k = 0; k < 4; k++) {
                vl[k][p] = __expf(vl[k][p] - M[2 * p]);
                s1 += vl[k][p];
                vh[k][p] = __expf(vh[k][p] - M[2 * p + 1]);
                s2 += vh[k][p];
            }
            sl[p]  = wred_sum(s1);
            sh2[p] = wred_sum(s2);
        }
        if (lane == 0) {
#pragma unroll
            for (int p = 0; p < 4; p++) {
                redsum[warp][2 * p]     = sl[p];
                redsum[warp][2 * p + 1] = sh2[p];
            }
        }
        __syncthreads();
        float R[8];
#pragma unroll
        for (int nn = 0; nn < 8; nn++)
            R[nn] = 1.0f / (redsum[0][nn] + redsum[1][nn] +
                            redsum[2][nn] + redsum[3][nn]);

#pragma unroll
        for (int p = 0; p < 4; p++) {
            fp0 += vl[0][p] * R[2 * p] + vh[0][p] * R[2 * p + 1];
            fp1 += vl[1][p] * R[2 * p] + vh[1][p] * R[2 * p + 1];
            fp2 += vl[2][p] * R[2 * p] + vh[2][p] * R[2 * p + 1];
            fp3 += vl[3][p] * R[2 * p] + vh[3][p] * R[2 * p + 1];
        }
    }

    float* po = out + b * OUTD + (tid << 2);
    atomicAdd(po + 0, fp0);
    atomicAdd(po + 1, fp1);
    atomicAdd(po + 2, fp2);
    atomicAdd(po + 3, fp3);
}

// ---------------- launch ----------------
extern "C" void kernel_launch(void* const* d_in, const int* in_sizes, int n_in,
                              void* d_out, int out_size) {
    const float* graph = (const float*)d_in[0];
    const float* Wi    = (const float*)d_in[1];
    const float* bi    = (const float*)d_in[2];
    const float* Wo    = (const float*)d_in[3];
    const float* bo    = (const float*)d_in[4];
    float* out = (float*)d_out;

    k_rowsum<<<NB * NN / 2, FCH * 8>>>(graph, out);
    dim3 gc(NB, 4);
    k_cores<<<gc, 128>>>(Wi, bi);
    dim3 gg(NB, 4, 3);
    k_gemm<<<gg, 128>>>(Wo, bo, out);
}

// round 6
// speedup vs baseline: 1.0783x; 1.0783x over previous
#include <cuda_runtime.h>

#define NB 128
#define NN 128
#define INNER 40
#define OUTD 512
#define FCH 41
#define ROWF (NN * FCH)          // 5248 floats per (b,i) row
#define ROWQ (ROWF / 4)          // 1312 float4

typedef unsigned long long ull;

// Scratch (allocation-free: device globals)
__device__ float g_S0[NB * NN * INNER];     // row sums over j of g[b,i,j,f], f<40
__device__ float g_core0[NB * NN * INNER];  // diagonal attrs g[b,i,i,f], f<40
__device__ float g_bonds[NB * NN * NN];     // g[b,i,j,40] laid out [b][i][j]
__device__ float g_cores[3 * NB * NN * INNER]; // [d][b][grp][f][n32]

// ---------------- helpers ----------------
__device__ __forceinline__ ull pk(float a, float b) {
    ull r;
    asm("mov.b64 %0, {%1,%2};" : "=l"(r) : "f"(a), "f"(b));
    return r;
}
__device__ __forceinline__ ull fma2(ull a, ull b, ull c) {
    ull d;
    asm("fma.rn.f32x2 %0, %1, %2, %3;" : "=l"(d) : "l"(a), "l"(b), "l"(c));
    return d;
}
__device__ __forceinline__ float lo64(ull v) { return __uint_as_float((unsigned)v); }
__device__ __forceinline__ float hi64(ull v) { return __uint_as_float((unsigned)(v >> 32)); }

struct ull2x { ull x, y; };

__device__ __forceinline__ float wred_max(float v) {
#pragma unroll
    for (int o = 16; o; o >>= 1) v = fmaxf(v, __shfl_xor_sync(0xffffffffu, v, o));
    return v;
}
__device__ __forceinline__ float wred_sum(float v) {
#pragma unroll
    for (int o = 16; o; o >>= 1) v += __shfl_xor_sync(0xffffffffu, v, o);
    return v;
}

// ---------------- kernel 1: streaming row reduction, 2 rows per block ----------------
// 4*328 = 1312 = 32*41: thread t, float4 slot t+328s -> element k has channel
// f_k = (4t+k) % 41 constant in s, j = (4t+k)/41 + 32s. MLP=8 front-batched loads.
// __launch_bounds__(328,3): force 3 resident blocks (33 warps/SM).
__global__ void __launch_bounds__(FCH * 8, 3) k_rowsum(const float* __restrict__ g,
                                                       float* __restrict__ out) {
    const int pr   = blockIdx.x;         // row pair 0..8191
    const int row0 = pr * 2;
    const int t    = threadIdx.x;        // 0..327
    const float4* base = reinterpret_cast<const float4*>(g + (long long)row0 * ROWF);

    __shared__ float s_flat[2][FCH * 32];   // per-row channel partials

    if (t < 2) reinterpret_cast<float4*>(out)[row0 + t] = make_float4(0.f, 0.f, 0.f, 0.f);

    float4 v[8];
#pragma unroll
    for (int s = 0; s < 4; s++) {
        v[s]     = base[t + 328 * s];
        v[4 + s] = base[ROWQ + t + 328 * s];
    }

    int f4[4], jb[4];
#pragma unroll
    for (int k = 0; k < 4; k++) {
        int e = 4 * t + k;
        f4[k] = e % FCH;
        jb[k] = e / FCH;
    }

#pragma unroll
    for (int r = 0; r < 2; r++) {
        const int row = row0 + r;
        const int i   = row & (NN - 1);
        float* brow = g_bonds + row * NN;
        float acc0 = 0.f, acc1 = 0.f, acc2 = 0.f, acc3 = 0.f;
#pragma unroll
        for (int s = 0; s < 4; s++) {
            float4 x = v[4 * r + s];
            const int j0 = 32 * s;
            if (f4[0] == FCH - 1) brow[jb[0] + j0] = x.x;
            else { acc0 += x.x; if (jb[0] + j0 == i) g_core0[row * INNER + f4[0]] = x.x; }
            if (f4[1] == FCH - 1) brow[jb[1] + j0] = x.y;
            else { acc1 += x.y; if (jb[1] + j0 == i) g_core0[row * INNER + f4[1]] = x.y; }
            if (f4[2] == FCH - 1) brow[jb[2] + j0] = x.z;
            else { acc2 += x.z; if (jb[2] + j0 == i) g_core0[row * INNER + f4[2]] = x.z; }
            if (f4[3] == FCH - 1) brow[jb[3] + j0] = x.w;
            else { acc3 += x.w; if (jb[3] + j0 == i) g_core0[row * INNER + f4[3]] = x.w; }
        }
        *reinterpret_cast<float4*>(&s_flat[r][4 * t]) = make_float4(acc0, acc1, acc2, acc3);
    }
    __syncthreads();

    if (t < INNER) {
        float t0 = 0.f, t1 = 0.f;
#pragma unroll
        for (int m = 0; m < 32; m++) {     // stride 41 mod 32 = 9, gcd(9,32)=1 -> conflict-free
            t0 += s_flat[0][t + FCH * m];
            t1 += s_flat[1][t + FCH * m];
        }
        g_S0[row0 * INNER + t]       = t0;
        g_S0[(row0 + 1) * INNER + t] = t1;
    }
}

// ---------------- kernel 2: compute the three cores ----------------
// grid (128, 4), block 128. Output layout [d][b][grp][f][n32] (coalesced both ends).
__global__ void __launch_bounds__(128) k_cores(
    const float* __restrict__ Wi,   // (3,40,40)
    const float* __restrict__ bi)   // (3,1,40)
{
    const int b   = blockIdx.x;
    const int grp = blockIdx.y;
    const int i0  = grp * 32;
    const int tid = threadIdx.x;
    const int warp = tid >> 5, lane = tid & 31;

    __shared__ float shA[32][INNER + 1];   // S0, later pre2
    __shared__ float shC0[32][INNER + 1];  // core0
    __shared__ float shc[32];
    __shared__ float shcp[4][32];
    __shared__ float cores[3][INNER][32];

    for (int idx = tid; idx < 32 * INNER; idx += 128) {
        int n = idx / INNER, f2 = idx % INNER;
        int row = b * NN + i0 + n;
        shA[n][f2] = g_S0[row * INNER + f2];
        float cv = g_core0[row * INNER + f2];
        shC0[n][f2] = cv;
        cores[0][f2][n] = cv;
    }
    {
        const float* bb = g_bonds + (b * NN) * NN + i0 + lane;
        float cp = 0.f;
#pragma unroll 8
        for (int m = 0; m < 32; m++)
            cp += bb[(warp + 4 * m) * NN];
        shcp[warp][lane] = cp;
    }
    __syncthreads();
    if (tid < 32)
        shc[tid] = 1.0f + shcp[0][tid] + shcp[1][tid] + shcp[2][tid] + shcp[3][tid];
    __syncthreads();

    for (int idx = tid; idx < INNER * 32; idx += 128) {
        int fp = idx >> 5, n = idx & 31;
        float s = bi[INNER + fp];
#pragma unroll
        for (int f2 = 0; f2 < INNER; f2++)
            s = fmaf(shA[n][f2], Wi[INNER * INNER + f2 * INNER + fp], s);
        cores[1][fp][n] = s;
    }
    __syncthreads();

    for (int idx = tid; idx < INNER * 32; idx += 128) {
        int f2 = idx >> 5, n = idx & 31;
        float d1 = cores[1][f2][n] - shC0[n][f2];
        shA[n][f2] = fmaf(shc[n], d1, shA[n][f2]);
    }
    __syncthreads();

    for (int idx = tid; idx < INNER * 32; idx += 128) {
        int fp = idx >> 5, n = idx & 31;
        float s = bi[2 * INNER + fp];
#pragma unroll
        for (int f2 = 0; f2 < INNER; f2++)
            s = fmaf(shA[n][f2], Wi[2 * INNER * INNER + f2 * INNER + fp], s);
        cores[2][fp][n] = s;
    }
    __syncthreads();

    // write out: idx = d*1280 + f*32 + n -> fully coalesced
    for (int idx = tid; idx < 3 * 32 * INNER; idx += 128) {
        int n = idx & 31;
        int f2 = (idx >> 5) % INNER;
        int d = idx / (32 * INNER);
        g_cores[((d * NB + b) * 4 + grp) * (32 * INNER) + f2 * 32 + n] = cores[d][f2][n];
    }
}

// ---------------- kernel 3: logits GEMM + softmax + fp ----------------
// grid (128, 4, 3). Accumulate over OUTPUT pairs: W consumed directly as ull2
// (no duplication movs); cores stored pre-duplicated pk(c,c) in smem.
__global__ void __launch_bounds__(128) k_gemm(
    const float* __restrict__ Wo,   // (3,40,512)
    const float* __restrict__ bo,   // (3,1,512)
    float* __restrict__ out)        // (128,512)
{
    const int b   = blockIdx.x;
    const int grp = blockIdx.y;
    const int d   = blockIdx.z;
    const int tid = threadIdx.x;
    const int warp = tid >> 5, lane = tid & 31;

    __shared__ __align__(16) ull sC[INNER * 32];  // pk(core,core), flat [f][n]
    __shared__ float redmax[4][8];
    __shared__ float redsum[4][8];

    // stage cores, pre-duplicated
    {
        const float* src = g_cores + ((d * NB + b) * 4 + grp) * (32 * INNER);
        for (int idx = tid; idx < INNER * 32; idx += 128) {
            float v = src[idx];
            sC[idx] = pk(v, v);
        }
    }
    __syncthreads();

    const ull2x* Wd = reinterpret_cast<const ull2x*>(Wo + d * (INNER * OUTD) + (tid << 2));
    const ull2x bias = *reinterpret_cast<const ull2x*>(bo + d * OUTD + (tid << 2));

    float fp0 = 0.f, fp1 = 0.f, fp2 = 0.f, fp3 = 0.f;

    for (int ch = 0; ch < 4; ch++) {   // 8 nodes per chunk
        ull a0[8], a1[8];
#pragma unroll
        for (int n = 0; n < 8; n++) { a0[n] = bias.x; a1[n] = bias.y; }

        const ull2x* cr = reinterpret_cast<const ull2x*>(sC + ch * 8);
#pragma unroll 8
        for (int f2 = 0; f2 < INNER; f2++) {
            ull2x w = Wd[f2 * (OUTD / 4)];
            ull2x c01 = cr[f2 * 16 + 0];
            ull2x c23 = cr[f2 * 16 + 1];
            ull2x c45 = cr[f2 * 16 + 2];
            ull2x c67 = cr[f2 * 16 + 3];
            a0[0] = fma2(c01.x, w.x, a0[0]);  a1[0] = fma2(c01.x, w.y, a1[0]);
            a0[1] = fma2(c01.y, w.x, a0[1]);  a1[1] = fma2(c01.y, w.y, a1[1]);
            a0[2] = fma2(c23.x, w.x, a0[2]);  a1[2] = fma2(c23.x, w.y, a1[2]);
            a0[3] = fma2(c23.y, w.x, a0[3]);  a1[3] = fma2(c23.y, w.y, a1[3]);
            a0[4] = fma2(c45.x, w.x, a0[4]);  a1[4] = fma2(c45.x, w.y, a1[4]);
            a0[5] = fma2(c45.y, w.x, a0[5]);  a1[5] = fma2(c45.y, w.y, a1[5]);
            a0[6] = fma2(c67.x, w.x, a0[6]);  a1[6] = fma2(c67.x, w.y, a1[6]);
            a0[7] = fma2(c67.y, w.x, a0[7]);  a1[7] = fma2(c67.y, w.y, a1[7]);
        }

        // unpack: node n outputs {lo a0, hi a0, lo a1, hi a1} = o 4t..4t+3
        float v[8][4];
#pragma unroll
        for (int n = 0; n < 8; n++) {
            v[n][0] = lo64(a0[n]); v[n][1] = hi64(a0[n]);
            v[n][2] = lo64(a1[n]); v[n][3] = hi64(a1[n]);
        }

        // per-node max over 512 outputs
        float mx[8];
#pragma unroll
        for (int n = 0; n < 8; n++) {
            mx[n] = wred_max(fmaxf(fmaxf(v[n][0], v[n][1]), fmaxf(v[n][2], v[n][3])));
        }
        if (lane == 0) {
#pragma unroll
            for (int n = 0; n < 8; n++) redmax[warp][n] = mx[n];
        }
        __syncthreads();
        float M[8];
#pragma unroll
        for (int n = 0; n < 8; n++)
            M[n] = fmaxf(fmaxf(redmax[0][n], redmax[1][n]),
                         fmaxf(redmax[2][n], redmax[3][n]));

        float sm[8];
#pragma unroll
        for (int n = 0; n < 8; n++) {
            float s = 0.f;
#pragma unroll
            for (int k = 0; k < 4; k++) {
                v[n][k] = __expf(v[n][k] - M[n]);
                s += v[n][k];
            }
            sm[n] = wred_sum(s);
        }
        if (lane == 0) {
#pragma unroll
            for (int n = 0; n < 8; n++) redsum[warp][n] = sm[n];
        }
        __syncthreads();

#pragma unroll
        for (int n = 0; n < 8; n++) {
            float R = 1.0f / (redsum[0][n] + redsum[1][n] + redsum[2][n] + redsum[3][n]);
            fp0 += v[n][0] * R;
            fp1 += v[n][1] * R;
            fp2 += v[n][2] * R;
            fp3 += v[n][3] * R;
        }
    }

    float* po = out + b * OUTD + (tid << 2);
    atomicAdd(po + 0, fp0);
    atomicAdd(po + 1, fp1);
    atomicAdd(po + 2, fp2);
    atomicAdd(po + 3, fp3);
}

// ---------------- launch ----------------
extern "C" void kernel_launch(void* const* d_in, const int* in_sizes, int n_in,
                              void* d_out, int out_size) {
    const float* graph = (const float*)d_in[0];
    const float* Wi    = (const float*)d_in[1];
    const float* bi    = (const float*)d_in[2];
    const float* Wo    = (const float*)d_in[3];
    const float* bo    = (const float*)d_in[4];
    float* out = (float*)d_out;

    k_rowsum<<<NB * NN / 2, FCH * 8>>>(graph, out);
    dim3 gc(NB, 4);
    k_cores<<<gc, 128>>>(Wi, bi);
    dim3 gg(NB, 4, 3);
    k_gemm<<<gg, 128>>>(Wo, bo, out);
}

// round 10
// speedup vs baseline: 1.1171x; 1.0360x over previous
#include <cuda_runtime.h>

#define NB 128
#define NN 128
#define INNER 40
#define OUTD 512
#define FCH 41
#define ROWF (NN * FCH)          // 5248 floats per (b,i) row
#define ROWQ (ROWF / 4)          // 1312 float4

typedef unsigned long long ull;

// Scratch (allocation-free: device globals)
__device__ float g_S0[NB * NN * INNER];     // row sums over j of g[b,i,j,f], f<40
__device__ float g_core0[NB * NN * INNER];  // diagonal attrs g[b,i,i,f], f<40
__device__ float g_bonds[NB * NN * NN];     // g[b,i,j,40] laid out [b][i][j]
__device__ float g_cores[3 * NB * NN * INNER]; // [d][b][grp][f][n32]

// ---------------- helpers ----------------
__device__ __forceinline__ ull pk(float a, float b) {
    ull r;
    asm("mov.b64 %0, {%1,%2};" : "=l"(r) : "f"(a), "f"(b));
    return r;
}
__device__ __forceinline__ ull fma2(ull a, ull b, ull c) {
    ull d;
    asm("fma.rn.f32x2 %0, %1, %2, %3;" : "=l"(d) : "l"(a), "l"(b), "l"(c));
    return d;
}
__device__ __forceinline__ float lo64(ull v) { return __uint_as_float((unsigned)v); }
__device__ __forceinline__ float hi64(ull v) { return __uint_as_float((unsigned)(v >> 32)); }

struct ull2x { ull x, y; };

__device__ __forceinline__ float wred_max(float v) {
#pragma unroll
    for (int o = 16; o; o >>= 1) v = fmaxf(v, __shfl_xor_sync(0xffffffffu, v, o));
    return v;
}
__device__ __forceinline__ float wred_sum(float v) {
#pragma unroll
    for (int o = 16; o; o >>= 1) v += __shfl_xor_sync(0xffffffffu, v, o);
    return v;
}

// ---------------- kernel 1: streaming row reduction, 2 rows per block ----------------
// (unchanged — measured 62.3 us @ 72.5% DRAM)
__global__ void __launch_bounds__(FCH * 8, 3) k_rowsum(const float* __restrict__ g,
                                                       float* __restrict__ out) {
    const int pr   = blockIdx.x;         // row pair 0..8191
    const int row0 = pr * 2;
    const int t    = threadIdx.x;        // 0..327
    const float4* base = reinterpret_cast<const float4*>(g + (long long)row0 * ROWF);

    __shared__ float s_flat[2][FCH * 32];   // per-row channel partials

    if (t < 2) reinterpret_cast<float4*>(out)[row0 + t] = make_float4(0.f, 0.f, 0.f, 0.f);

    float4 v[8];
#pragma unroll
    for (int s = 0; s < 4; s++) {
        v[s]     = base[t + 328 * s];
        v[4 + s] = base[ROWQ + t + 328 * s];
    }

    int f4[4], jb[4];
#pragma unroll
    for (int k = 0; k < 4; k++) {
        int e = 4 * t + k;
        f4[k] = e % FCH;
        jb[k] = e / FCH;
    }

#pragma unroll
    for (int r = 0; r < 2; r++) {
        const int row = row0 + r;
        const int i   = row & (NN - 1);
        float* brow = g_bonds + row * NN;
        float acc0 = 0.f, acc1 = 0.f, acc2 = 0.f, acc3 = 0.f;
#pragma unroll
        for (int s = 0; s < 4; s++) {
            float4 x = v[4 * r + s];
            const int j0 = 32 * s;
            if (f4[0] == FCH - 1) brow[jb[0] + j0] = x.x;
            else { acc0 += x.x; if (jb[0] + j0 == i) g_core0[row * INNER + f4[0]] = x.x; }
            if (f4[1] == FCH - 1) brow[jb[1] + j0] = x.y;
            else { acc1 += x.y; if (jb[1] + j0 == i) g_core0[row * INNER + f4[1]] = x.y; }
            if (f4[2] == FCH - 1) brow[jb[2] + j0] = x.z;
            else { acc2 += x.z; if (jb[2] + j0 == i) g_core0[row * INNER + f4[2]] = x.z; }
            if (f4[3] == FCH - 1) brow[jb[3] + j0] = x.w;
            else { acc3 += x.w; if (jb[3] + j0 == i) g_core0[row * INNER + f4[3]] = x.w; }
        }
        *reinterpret_cast<float4*>(&s_flat[r][4 * t]) = make_float4(acc0, acc1, acc2, acc3);
    }
    __syncthreads();

    if (t < INNER) {
        float t0 = 0.f, t1 = 0.f;
#pragma unroll
        for (int m = 0; m < 32; m++) {     // stride 41 mod 32 = 9, gcd(9,32)=1 -> conflict-free
            t0 += s_flat[0][t + FCH * m];
            t1 += s_flat[1][t + FCH * m];
        }
        g_S0[row0 * INNER + t]       = t0;
        g_S0[(row0 + 1) * INNER + t] = t1;
    }
}

// ---------------- kernel 2: compute the three cores (unchanged) ----------------
__global__ void __launch_bounds__(128) k_cores(
    const float* __restrict__ Wi,   // (3,40,40)
    const float* __restrict__ bi)   // (3,1,40)
{
    const int b   = blockIdx.x;
    const int grp = blockIdx.y;
    const int i0  = grp * 32;
    const int tid = threadIdx.x;
    const int warp = tid >> 5, lane = tid & 31;

    __shared__ float shA[32][INNER + 1];   // S0, later pre2
    __shared__ float shC0[32][INNER + 1];  // core0
    __shared__ float shc[32];
    __shared__ float shcp[4][32];
    __shared__ float cores[3][INNER][32];

    for (int idx = tid; idx < 32 * INNER; idx += 128) {
        int n = idx / INNER, f2 = idx % INNER;
        int row = b * NN + i0 + n;
        shA[n][f2] = g_S0[row * INNER + f2];
        float cv = g_core0[row * INNER + f2];
        shC0[n][f2] = cv;
        cores[0][f2][n] = cv;
    }
    {
        const float* bb = g_bonds + (b * NN) * NN + i0 + lane;
        float cp = 0.f;
#pragma unroll 8
        for (int m = 0; m < 32; m++)
            cp += bb[(warp + 4 * m) * NN];
        shcp[warp][lane] = cp;
    }
    __syncthreads();
    if (tid < 32)
        shc[tid] = 1.0f + shcp[0][tid] + shcp[1][tid] + shcp[2][tid] + shcp[3][tid];
    __syncthreads();

    for (int idx = tid; idx < INNER * 32; idx += 128) {
        int fp = idx >> 5, n = idx & 31;
        float s = bi[INNER + fp];
#pragma unroll
        for (int f2 = 0; f2 < INNER; f2++)
            s = fmaf(shA[n][f2], Wi[INNER * INNER + f2 * INNER + fp], s);
        cores[1][fp][n] = s;
    }
    __syncthreads();

    for (int idx = tid; idx < INNER * 32; idx += 128) {
        int f2 = idx >> 5, n = idx & 31;
        float d1 = cores[1][f2][n] - shC0[n][f2];
        shA[n][f2] = fmaf(shc[n], d1, shA[n][f2]);
    }
    __syncthreads();

    for (int idx = tid; idx < INNER * 32; idx += 128) {
        int fp = idx >> 5, n = idx & 31;
        float s = bi[2 * INNER + fp];
#pragma unroll
        for (int f2 = 0; f2 < INNER; f2++)
            s = fmaf(shA[n][f2], Wi[2 * INNER * INNER + f2 * INNER + fp], s);
        cores[2][fp][n] = s;
    }
    __syncthreads();

    for (int idx = tid; idx < 3 * 32 * INNER; idx += 128) {
        int n = idx & 31;
        int f2 = (idx >> 5) % INNER;
        int d = idx / (32 * INNER);
        g_cores[((d * NB + b) * 4 + grp) * (32 * INNER) + f2 * 32 + n] = cores[d][f2][n];
    }
}

// ---------------- kernel 3: logits GEMM + softmax + fp ----------------
// grid (128, 4, 3), block 128 = 2 teams x 64 threads.
// Team tm handles nodes [16*tm, 16*tm+16) in 2 passes of 8 nodes.
// Thread u (0..63) owns cols {4u..4u+3} U {256+4u..256+4u+3}: both per-warp
// LDG.128s are line-dense (8 wavefronts/f2 total vs FMA 16 SM-cyc -> FMA-bound).
__global__ void __launch_bounds__(128, 4) k_gemm(
    const float* __restrict__ Wo,   // (3,40,512)
    const float* __restrict__ bo,   // (3,1,512)
    float* __restrict__ out)        // (128,512)
{
    const int b   = blockIdx.x;
    const int grp = blockIdx.y;
    const int d   = blockIdx.z;
    const int tid = threadIdx.x;
    const int warp = tid >> 5, lane = tid & 31;
    const int tm  = tid >> 6;       // team 0/1
    const int u   = tid & 63;       // col-octet owner

    __shared__ __align__(16) ull sC[INNER * 32];  // pk(core,core), flat [f][n]
    __shared__ float redm[4][8];
    __shared__ float reds[4][8];

    // stage cores, pre-duplicated
    {
        const float* src = g_cores + ((d * NB + b) * 4 + grp) * (32 * INNER);
        for (int idx = tid; idx < INNER * 32; idx += 128) {
            float v = src[idx];
            sC[idx] = pk(v, v);
        }
    }
    __syncthreads();

    const float* Wd = Wo + d * (INNER * OUTD) + (u << 2);
    const ull2x ba = *reinterpret_cast<const ull2x*>(bo + d * OUTD + (u << 2));
    const ull2x bb = *reinterpret_cast<const ull2x*>(bo + d * OUTD + 256 + (u << 2));

    float fpa[8] = {0.f, 0.f, 0.f, 0.f, 0.f, 0.f, 0.f, 0.f};

#pragma unroll 1
    for (int p = 0; p < 2; p++) {
        const int bn = tm * 16 + p * 8;  // first node of this pass

        ull acc[8][4];
#pragma unroll
        for (int n = 0; n < 8; n++) {
            acc[n][0] = ba.x; acc[n][1] = ba.y;
            acc[n][2] = bb.x; acc[n][3] = bb.y;
        }

        const float* wp = Wd;
        const ull2x* cp2 = reinterpret_cast<const ull2x*>(sC + bn);
#pragma unroll 4
        for (int f2 = 0; f2 < INNER; f2++, wp += OUTD, cp2 += 16) {
            ull2x wa = *reinterpret_cast<const ull2x*>(wp);        // cols 4u..4u+3
            ull2x wb = *reinterpret_cast<const ull2x*>(wp + 256);  // cols 256+4u..
            ull2x c01 = cp2[0], c23 = cp2[1], c45 = cp2[2], c67 = cp2[3];

            acc[0][0]=fma2(c01.x, wa.x, acc[0][0]); acc[0][1]=fma2(c01.x, wa.y, acc[0][1]);
            acc[0][2]=fma2(c01.x, wb.x, acc[0][2]); acc[0][3]=fma2(c01.x, wb.y, acc[0][3]);
            acc[1][0]=fma2(c01.y, wa.x, acc[1][0]); acc[1][1]=fma2(c01.y, wa.y, acc[1][1]);
            acc[1][2]=fma2(c01.y, wb.x, acc[1][2]); acc[1][3]=fma2(c01.y, wb.y, acc[1][3]);
            acc[2][0]=fma2(c23.x, wa.x, acc[2][0]); acc[2][1]=fma2(c23.x, wa.y, acc[2][1]);
            acc[2][2]=fma2(c23.x, wb.x, acc[2][2]); acc[2][3]=fma2(c23.x, wb.y, acc[2][3]);
            acc[3][0]=fma2(c23.y, wa.x, acc[3][0]); acc[3][1]=fma2(c23.y, wa.y, acc[3][1]);
            acc[3][2]=fma2(c23.y, wb.x, acc[3][2]); acc[3][3]=fma2(c23.y, wb.y, acc[3][3]);
            acc[4][0]=fma2(c45.x, wa.x, acc[4][0]); acc[4][1]=fma2(c45.x, wa.y, acc[4][1]);
            acc[4][2]=fma2(c45.x, wb.x, acc[4][2]); acc[4][3]=fma2(c45.x, wb.y, acc[4][3]);
            acc[5][0]=fma2(c45.y, wa.x, acc[5][0]); acc[5][1]=fma2(c45.y, wa.y, acc[5][1]);
            acc[5][2]=fma2(c45.y, wb.x, acc[5][2]); acc[5][3]=fma2(c45.y, wb.y, acc[5][3]);
            acc[6][0]=fma2(c67.x, wa.x, acc[6][0]); acc[6][1]=fma2(c67.x, wa.y, acc[6][1]);
            acc[6][2]=fma2(c67.x, wb.x, acc[6][2]); acc[6][3]=fma2(c67.x, wb.y, acc[6][3]);
            acc[7][0]=fma2(c67.y, wa.x, acc[7][0]); acc[7][1]=fma2(c67.y, wa.y, acc[7][1]);
            acc[7][2]=fma2(c67.y, wb.x, acc[7][2]); acc[7][3]=fma2(c67.y, wb.y, acc[7][3]);
        }

        // unpack: node n, 8 cols {4u+0..3, 256+4u+0..3}
        float v[8][8];
#pragma unroll
        for (int n = 0; n < 8; n++) {
            v[n][0] = lo64(acc[n][0]); v[n][1] = hi64(acc[n][0]);
            v[n][2] = lo64(acc[n][1]); v[n][3] = hi64(acc[n][1]);
            v[n][4] = lo64(acc[n][2]); v[n][5] = hi64(acc[n][2]);
            v[n][6] = lo64(acc[n][3]); v[n][7] = hi64(acc[n][3]);
        }

        // per-node max over 512 outputs (8 local -> warp -> team of 2 warps)
#pragma unroll
        for (int n = 0; n < 8; n++) {
            float m = v[n][0];
#pragma unroll
            for (int k = 1; k < 8; k++) m = fmaxf(m, v[n][k]);
            m = wred_max(m);
            if (lane == 0) redm[warp][n] = m;
        }
        __syncthreads();
        float M[8];
#pragma unroll
        for (int n = 0; n < 8; n++)
            M[n] = fmaxf(redm[2 * tm][n], redm[2 * tm + 1][n]);

        // exp + per-node sum
#pragma unroll
        for (int n = 0; n < 8; n++) {
            float s = 0.f;
#pragma unroll
            for (int k = 0; k < 8; k++) {
                v[n][k] = __expf(v[n][k] - M[n]);
                s += v[n][k];
            }
            s = wred_sum(s);
            if (lane == 0) reds[warp][n] = s;
        }
        __syncthreads();

#pragma unroll
        for (int n = 0; n < 8; n++) {
            float R = 1.0f / (reds[2 * tm][n] + reds[2 * tm + 1][n]);
#pragma unroll
            for (int k = 0; k < 8; k++) fpa[k] += v[n][k] * R;
        }
        __syncthreads();   // protect redm/reds before next pass overwrites
    }

    float* po = out + b * OUTD + (u << 2);
#pragma unroll
    for (int k = 0; k < 4; k++) atomicAdd(po + k, fpa[k]);
#pragma unroll
    for (int k = 0; k < 4; k++) atomicAdd(po + 256 + k, fpa[4 + k]);
}

// ---------------- launch ----------------
extern "C" void kernel_launch(void* const* d_in, const int* in_sizes, int n_in,
                              void* d_out, int out_size) {
    const float* graph = (const float*)d_in[0];
    const float* Wi    = (const float*)d_in[1];
    const float* bi    = (const float*)d_in[2];
    const float* Wo    = (const float*)d_in[3];
    const float* bo    = (const float*)d_in[4];
    float* out = (float*)d_out;

    k_rowsum<<<NB * NN / 2, FCH * 8>>>(graph, out);
    dim3 gc(NB, 4);
    k_cores<<<gc, 128>>>(Wi, bi);
    dim3 gg(NB, 4, 3);
    k_gemm<<<gg, 128>>>(Wo, bo, out);
}